// round 7
// baseline (speedup 1.0000x reference)
#include <cuda_runtime.h>
#include <cuda_bf16.h>
#include <math.h>
#include <cstdint>

#define N 8192
#define D 512

// Scratch
__device__ float g_K[(size_t)N * N];              // d2 (kept for maxP/final)
__device__ __nv_bfloat16 g_Kb[(size_t)N * N];     // bf16 K for matvecs
__device__ __nv_bfloat16 g_Xh[(size_t)N * D];
__device__ __nv_bfloat16 g_Xl[(size_t)N * D];
__device__ float g_part[64 * (size_t)N];          // symmetric-matvec partials (2MB)
__device__ float g_sq[N];
__device__ float g_u[N];
__device__ float g_v[N];
__device__ int g_maxd2_bits;
__device__ int g_maxP_bits;

__device__ __forceinline__ float2 bf2f(uint32_t u) {
    return __bfloat1622float2(*(const __nv_bfloat162*)&u);
}
__device__ __forceinline__ uint32_t smem_u32(const void* p) {
    uint32_t a;
    asm("{ .reg .u64 t; cvta.to.shared.u64 t, %1; cvt.u32.u64 %0, t; }" : "=r"(a) : "l"(p));
    return a;
}
__device__ __forceinline__ void cpa(uint32_t d, const void* s) {
    asm volatile("cp.async.cg.shared.global [%0], [%1], 16;" :: "r"(d), "l"(s) : "memory");
}
#define CP_COMMIT() asm volatile("cp.async.commit_group;" ::: "memory")
#define CP_WAIT(n)  asm volatile("cp.async.wait_group %0;" :: "n"(n) : "memory")

// ---------------------------------------------------------------------------
__global__ void k_init() {
    int t = blockIdx.x * blockDim.x + threadIdx.x;
    if (t < N) g_v[t] = 1.0f;
    if (t == 0) { g_maxd2_bits = 0; g_maxP_bits = 0; }
}

__global__ void k_split(const float* __restrict__ X) {
    int i = blockIdx.x * blockDim.x + threadIdx.x;  // over N*D/4
    const float4* X4 = (const float4*)X;
    float4 x = X4[i];
    __nv_bfloat16 h0 = __float2bfloat16(x.x), h1 = __float2bfloat16(x.y);
    __nv_bfloat16 h2 = __float2bfloat16(x.z), h3 = __float2bfloat16(x.w);
    __nv_bfloat16 l0 = __float2bfloat16(x.x - __bfloat162float(h0));
    __nv_bfloat16 l1 = __float2bfloat16(x.y - __bfloat162float(h1));
    __nv_bfloat16 l2 = __float2bfloat16(x.z - __bfloat162float(h2));
    __nv_bfloat16 l3 = __float2bfloat16(x.w - __bfloat162float(h3));
    ((__nv_bfloat162*)g_Xh)[i * 2 + 0] = __nv_bfloat162(h0, h1);
    ((__nv_bfloat162*)g_Xh)[i * 2 + 1] = __nv_bfloat162(h2, h3);
    ((__nv_bfloat162*)g_Xl)[i * 2 + 0] = __nv_bfloat162(l0, l1);
    ((__nv_bfloat162*)g_Xl)[i * 2 + 1] = __nv_bfloat162(l2, l3);
}

__global__ void k_sq(const float* __restrict__ X) {
    int row = blockIdx.x;
    const float4* xr = (const float4*)(X + (size_t)row * D);
    float4 a = xr[threadIdx.x];
    float s = a.x * a.x + a.y * a.y + a.z * a.z + a.w * a.w;
    #pragma unroll
    for (int o = 16; o; o >>= 1) s += __shfl_down_sync(0xffffffffu, s, o);
    __shared__ float sh[4];
    if ((threadIdx.x & 31) == 0) sh[threadIdx.x >> 5] = s;
    __syncthreads();
    if (threadIdx.x == 0) g_sq[row] = sh[0] + sh[1] + sh[2] + sh[3];
}

// ---------------------------------------------------------------------------
// HMMA GEMM with cp.async 2-stage pipeline. 128x128 tile / CTA, K-chunk 32.
// d2 = sq_i + sq_j - 2*(Hi*Hi^T + Hi*Lo^T + Lo*Hi^T), fp32 accum.
// ---------------------------------------------------------------------------
#define PITCH2 80                 // bytes per SMEM row (32 bf16 + 16B pad)
#define TILE2  (128 * PITCH2)     // 10240
#define STAGE  (4 * TILE2)        // 40960
#define SM_GEMM (2 * STAGE)       // 81920

__device__ __forceinline__ void mma16816(float c[4], const uint32_t a[4], const uint32_t b[2]) {
    asm volatile(
        "mma.sync.aligned.m16n8k16.row.col.f32.bf16.bf16.f32 "
        "{%0,%1,%2,%3}, {%4,%5,%6,%7}, {%8,%9}, {%0,%1,%2,%3};"
        : "+f"(c[0]), "+f"(c[1]), "+f"(c[2]), "+f"(c[3])
        : "r"(a[0]), "r"(a[1]), "r"(a[2]), "r"(a[3]), "r"(b[0]), "r"(b[1]));
}
__device__ __forceinline__ void lda_frag(uint32_t f[4], const char* tile, int row, int kq) {
    const char* p = tile + row * PITCH2 + kq * 2;
    f[0] = *(const uint32_t*)(p);
    f[1] = *(const uint32_t*)(p + 8 * PITCH2);
    f[2] = *(const uint32_t*)(p + 16);
    f[3] = *(const uint32_t*)(p + 8 * PITCH2 + 16);
}
__device__ __forceinline__ void ldb_frag(uint32_t f[2], const char* tile, int n, int kq) {
    const char* p = tile + n * PITCH2 + kq * 2;
    f[0] = *(const uint32_t*)(p);
    f[1] = *(const uint32_t*)(p + 16);
}

__global__ void __launch_bounds__(256, 2) k_gemm_mma() {
    extern __shared__ __align__(16) char smem[];
    uint32_t sbase = smem_u32(smem);

    int tid = threadIdx.x, lane = tid & 31, wid = tid >> 5;
    int wm = wid & 3, wn = wid >> 2;  // 4 x 2 warps -> 32 x 64 per warp

    const int nT = N / 128;  // 64
    int b = blockIdx.x, bi = 0;
    while (b >= nT - bi) { b -= nT - bi; bi++; }
    int bj = bi + b;

    const __nv_bfloat16* gAh = g_Xh + (size_t)bi * 128 * D;
    const __nv_bfloat16* gAl = g_Xl + (size_t)bi * 128 * D;
    const __nv_bfloat16* gBh = g_Xh + (size_t)bj * 128 * D;
    const __nv_bfloat16* gBl = g_Xl + (size_t)bj * 128 * D;

    float acc[2][8][4];
    #pragma unroll
    for (int m = 0; m < 2; m++)
        #pragma unroll
        for (int n = 0; n < 8; n++)
            #pragma unroll
            for (int e = 0; e < 4; e++) acc[m][n][e] = 0.f;

    // issue async loads for chunk c into stage st (8 x 16B per thread)
    auto issue = [&](int st, int c) {
        int k0 = c * 32;
        #pragma unroll
        for (int e = 0; e < 2; e++) {
            int idx = e * 256 + tid;      // 0..511
            int row = idx >> 2;
            int seg = idx & 3;            // 16B segments
            size_t go = (size_t)row * D + k0 + seg * 8;
            uint32_t dofs = st * STAGE + row * PITCH2 + seg * 16;
            cpa(sbase + dofs,             gAh + go);
            cpa(sbase + dofs + TILE2,     gAl + go);
            cpa(sbase + dofs + 2 * TILE2, gBh + go);
            cpa(sbase + dofs + 3 * TILE2, gBl + go);
        }
        CP_COMMIT();
    };

    issue(0, 0);
    for (int c = 0; c < 16; c++) {
        if (c < 15) { issue((c + 1) & 1, c + 1); CP_WAIT(1); }
        else        { CP_WAIT(0); }
        __syncthreads();

        const char* sAh = smem + (c & 1) * STAGE;
        const char* sAl = sAh + TILE2;
        const char* sBh = sAh + 2 * TILE2;
        const char* sBl = sAh + 3 * TILE2;

        #pragma unroll
        for (int ks = 0; ks < 2; ks++) {
            int kq = ks * 16 + 2 * (lane & 3);
            int ra = wm * 32 + (lane >> 2);
            uint32_t ah0[4], ah1[4], al0[4], al1[4];
            lda_frag(ah0, sAh, ra, kq);
            lda_frag(ah1, sAh, ra + 16, kq);
            lda_frag(al0, sAl, ra, kq);
            lda_frag(al1, sAl, ra + 16, kq);
            #pragma unroll
            for (int nt = 0; nt < 8; nt++) {
                int nb = wn * 64 + nt * 8 + (lane >> 2);
                uint32_t bh[2], bl[2];
                ldb_frag(bh, sBh, nb, kq);
                ldb_frag(bl, sBl, nb, kq);
                mma16816(acc[0][nt], ah0, bh);
                mma16816(acc[1][nt], ah1, bh);
                mma16816(acc[0][nt], ah0, bl);
                mma16816(acc[1][nt], ah1, bl);
                mma16816(acc[0][nt], al0, bh);
                mma16816(acc[1][nt], al1, bh);
            }
        }
        __syncthreads();
    }

    // Epilogue: d2 = sq_i + sq_j - 2g; store + max; keep d2 in acc for mirror
    int row0 = bi * 128, col0 = bj * 128;
    float mx = 0.f;
    #pragma unroll
    for (int mt = 0; mt < 2; mt++) {
        #pragma unroll
        for (int half = 0; half < 2; half++) {
            int r = row0 + wm * 32 + mt * 16 + half * 8 + (lane >> 2);
            float si = g_sq[r];
            #pragma unroll
            for (int nt = 0; nt < 8; nt++) {
                int c = col0 + wn * 64 + nt * 8 + (lane & 3) * 2;
                float g0 = acc[mt][nt][half * 2 + 0];
                float g1 = acc[mt][nt][half * 2 + 1];
                float v0 = fmaxf(si + __ldg(&g_sq[c + 0]) - 2.f * g0, 0.f);
                float v1 = fmaxf(si + __ldg(&g_sq[c + 1]) - 2.f * g1, 0.f);
                mx = fmaxf(mx, fmaxf(v0, v1));
                acc[mt][nt][half * 2 + 0] = v0;
                acc[mt][nt][half * 2 + 1] = v1;
                *(float2*)&g_K[(size_t)r * N + c] = make_float2(v0, v1);
            }
        }
    }

    if (bi != bj) {  // mirror via SMEM transpose (coalesced write)
        __syncthreads();
        float* smT = (float*)smem;  // pitch 132 floats: 128*132*4 = 67584 <= 81920
        #pragma unroll
        for (int mt = 0; mt < 2; mt++)
            #pragma unroll
            for (int half = 0; half < 2; half++) {
                int rl = wm * 32 + mt * 16 + half * 8 + (lane >> 2);
                #pragma unroll
                for (int nt = 0; nt < 8; nt++) {
                    int cl = wn * 64 + nt * 8 + (lane & 3) * 2;
                    smT[(cl + 0) * 132 + rl] = acc[mt][nt][half * 2 + 0];
                    smT[(cl + 1) * 132 + rl] = acc[mt][nt][half * 2 + 1];
                }
            }
        __syncthreads();
        #pragma unroll
        for (int t = 0; t < 16; t++) {
            int i = t * 256 + tid;
            int rr = i >> 5;
            int c4 = (i & 31) * 4;
            float4 v = *(float4*)&smT[rr * 132 + c4];
            *(float4*)&g_K[(size_t)(col0 + rr) * N + row0 + c4] = v;
        }
    }

    __shared__ float red[256];
    red[tid] = mx;
    __syncthreads();
    for (int s = 128; s; s >>= 1) {
        if (tid < s) red[tid] = fmaxf(red[tid], red[tid + s]);
        __syncthreads();
    }
    if (tid == 0) atomicMax(&g_maxd2_bits, __float_as_int(red[0]));
}

// ---------------------------------------------------------------------------
// exp pass: Kb = bf16(exp(-10*sqrt(d2)/maxM)), diag -> 0.  d2 stays in g_K.
// ---------------------------------------------------------------------------
__global__ void k_exp() {
    const float inv_maxM = rsqrtf(__int_as_float(g_maxd2_bits));
    const int total4 = N * (N / 4);
    const float4* K4 = (const float4*)g_K;
    __nv_bfloat162* Kb2 = (__nv_bfloat162*)g_Kb;
    for (int idx = blockIdx.x * blockDim.x + threadIdx.x; idx < total4;
         idx += gridDim.x * blockDim.x) {
        int lin = idx << 2;
        int row = lin >> 13;
        int col = lin & (N - 1);
        float4 d = K4[idx];
        float r0 = (col + 0 == row) ? 0.f : __expf(-10.f * sqrtf(d.x) * inv_maxM);
        float r1 = (col + 1 == row) ? 0.f : __expf(-10.f * sqrtf(d.y) * inv_maxM);
        float r2 = (col + 2 == row) ? 0.f : __expf(-10.f * sqrtf(d.z) * inv_maxM);
        float r3 = (col + 3 == row) ? 0.f : __expf(-10.f * sqrtf(d.w) * inv_maxM);
        Kb2[idx * 2 + 0] = __nv_bfloat162(__float2bfloat16(r0), __float2bfloat16(r1));
        Kb2[idx * 2 + 1] = __nv_bfloat162(__float2bfloat16(r2), __float2bfloat16(r3));
    }
}

// ---------------------------------------------------------------------------
// Symmetric matvec: each upper-triangle tile read once; row + col partials.
// g_part[s][i]: strip-s partial of y[i]. Every slot written exactly once.
// ---------------------------------------------------------------------------
__global__ void __launch_bounds__(256) k_mv_sym(int dir) {
    const float* vin = dir ? g_u : g_v;
    __shared__ __align__(16) __nv_bfloat16 Ks[128 * 136];  // pitch 136 bf16 (272B)
    __shared__ float xi[128], xj[128];
    __shared__ float cpb[4 * 128];

    int b = blockIdx.x, bi = 0;
    while (b >= 64 - bi) { b -= 64 - bi; bi++; }
    int bj = bi + b;
    int row0 = bi << 7, col0 = bj << 7;
    int tid = threadIdx.x;

    if (tid < 128) { xi[tid] = vin[row0 + tid]; xj[tid] = vin[col0 + tid]; }
    __syncthreads();

    // load tile + row partial (thread t: row r = t>>1, col-half h = t&1)
    int r = tid >> 1, h = tid & 1;
    const uint4* src = (const uint4*)(g_Kb + (size_t)(row0 + r) * N + col0 + (h << 6));
    float s = 0.f;
    #pragma unroll
    for (int q = 0; q < 8; q++) {
        uint4 v = __ldg(&src[q]);
        *(uint4*)(Ks + r * 136 + (h << 6) + (q << 3)) = v;
        const float* xb = xj + (h << 6) + (q << 3);
        float2 p0 = bf2f(v.x), p1 = bf2f(v.y), p2 = bf2f(v.z), p3 = bf2f(v.w);
        s = fmaf(p0.x, xb[0], s); s = fmaf(p0.y, xb[1], s);
        s = fmaf(p1.x, xb[2], s); s = fmaf(p1.y, xb[3], s);
        s = fmaf(p2.x, xb[4], s); s = fmaf(p2.y, xb[5], s);
        s = fmaf(p3.x, xb[6], s); s = fmaf(p3.y, xb[7], s);
    }
    s += __shfl_down_sync(0xffffffffu, s, 1);
    if (h == 0) g_part[(size_t)bj * N + row0 + r] = s;

    if (bi != bj) {  // column partial: K_ij^T * x_i -> strip bi at block bj
        __syncthreads();
        int c0 = tid & 63, rg = tid >> 6;  // warp-uniform rg -> conflict-free
        float s0 = 0.f, s1 = 0.f;
        #pragma unroll
        for (int rr = 0; rr < 32; rr++) {
            int rowx = (rg << 5) + rr;
            uint32_t w = *(const uint32_t*)(Ks + rowx * 136 + (c0 << 1));
            float2 p = bf2f(w);
            float x = xi[rowx];
            s0 = fmaf(p.x, x, s0); s1 = fmaf(p.y, x, s1);
        }
        cpb[rg * 128 + (c0 << 1)] = s0;
        cpb[rg * 128 + (c0 << 1) + 1] = s1;
        __syncthreads();
        if (tid < 128) {
            float t = cpb[tid] + cpb[128 + tid] + cpb[256 + tid] + cpb[384 + tid];
            g_part[(size_t)bi * N + col0 + tid] = t;
        }
    }
}

__global__ void k_mv_reduce(int dir) {
    float* vout = dir ? g_v : g_u;
    int row = (blockIdx.x << 7) + threadIdx.x;
    float s = 0.f;
    #pragma unroll
    for (int k = 0; k < 64; k++) s += g_part[(size_t)k * N + row];
    vout[row] = 1.0f / s;
}

// ---------------------------------------------------------------------------
// maxP = max_ij u_i K_ij v_j, K recomputed from d2 (diag skipped)
// ---------------------------------------------------------------------------
__global__ void k_maxP() {
    const float inv_maxM = rsqrtf(__int_as_float(g_maxd2_bits));
    const int total4 = N * (N / 4);
    const float4* K4 = (const float4*)g_K;
    float m = 0.f;
    for (int idx = blockIdx.x * blockDim.x + threadIdx.x; idx < total4;
         idx += gridDim.x * blockDim.x) {
        int lin = idx << 2;
        int row = lin >> 13;
        int col = lin & (N - 1);
        float u = __ldg(&g_u[row]);
        float4 d = K4[idx];
        float4 vv = *(const float4*)(g_v + col);
        float e0 = (col + 0 == row) ? 0.f : __expf(-10.f * sqrtf(d.x) * inv_maxM);
        float e1 = (col + 1 == row) ? 0.f : __expf(-10.f * sqrtf(d.y) * inv_maxM);
        float e2 = (col + 2 == row) ? 0.f : __expf(-10.f * sqrtf(d.z) * inv_maxM);
        float e3 = (col + 3 == row) ? 0.f : __expf(-10.f * sqrtf(d.w) * inv_maxM);
        m = fmaxf(m, u * e0 * vv.x);
        m = fmaxf(m, u * e1 * vv.y);
        m = fmaxf(m, u * e2 * vv.z);
        m = fmaxf(m, u * e3 * vv.w);
    }
    #pragma unroll
    for (int o = 16; o; o >>= 1) m = fmaxf(m, __shfl_down_sync(0xffffffffu, m, o));
    __shared__ float sh[8];
    if ((threadIdx.x & 31) == 0) sh[threadIdx.x >> 5] = m;
    __syncthreads();
    if (threadIdx.x < 8) {
        float t = sh[threadIdx.x];
        #pragma unroll
        for (int o = 4; o; o >>= 1) t = fmaxf(t, __shfl_down_sync(0xffu, t, o));
        if (threadIdx.x == 0) atomicMax(&g_maxP_bits, __float_as_int(t));
    }
}

__global__ void k_final(float* __restrict__ out) {
    const float inv_maxM = rsqrtf(__int_as_float(g_maxd2_bits));
    const float invP = 1.0f / __int_as_float(g_maxP_bits);
    const int total4 = N * (N / 4);
    const float4* K4 = (const float4*)g_K;
    float4* O4 = (float4*)out;
    for (int idx = blockIdx.x * blockDim.x + threadIdx.x; idx < total4;
         idx += gridDim.x * blockDim.x) {
        int lin = idx << 2;
        int row = lin >> 13;
        int col = lin & (N - 1);
        float u = __ldg(&g_u[row]);
        float4 d = K4[idx];
        float4 vv = *(const float4*)(g_v + col);
        float4 r;
        r.x = (col + 0 == row) ? 1.f : u * __expf(-10.f * sqrtf(d.x) * inv_maxM) * vv.x * invP;
        r.y = (col + 1 == row) ? 1.f : u * __expf(-10.f * sqrtf(d.y) * inv_maxM) * vv.y * invP;
        r.z = (col + 2 == row) ? 1.f : u * __expf(-10.f * sqrtf(d.z) * inv_maxM) * vv.z * invP;
        r.w = (col + 3 == row) ? 1.f : u * __expf(-10.f * sqrtf(d.w) * inv_maxM) * vv.w * invP;
        O4[idx] = r;
    }
}

// ---------------------------------------------------------------------------
extern "C" void kernel_launch(void* const* d_in, const int* in_sizes, int n_in,
                              void* d_out, int out_size) {
    const float* X = (const float*)d_in[0];
    float* out = (float*)d_out;

    cudaFuncSetAttribute(k_gemm_mma, cudaFuncAttributeMaxDynamicSharedMemorySize, SM_GEMM);

    k_init<<<(N + 255) / 256, 256>>>();
    k_split<<<(N * D / 4) / 256, 256>>>(X);
    k_sq<<<N, 128>>>(X);
    k_gemm_mma<<<(64 * 65) / 2, 256, SM_GEMM>>>();
    k_exp<<<8192, 256>>>();
    for (int it = 0; it < 10; it++) {
        k_mv_sym<<<(64 * 65) / 2, 256>>>(0);   // partials of K*v
        k_mv_reduce<<<64, 128>>>(0);           // u = 1/(K v)
        k_mv_sym<<<(64 * 65) / 2, 256>>>(1);   // partials of K*u
        k_mv_reduce<<<64, 128>>>(1);           // v = 1/(K u)
    }
    k_maxP<<<8192, 256>>>();
    k_final<<<8192, 256>>>(out);
}

// round 12
// speedup vs baseline: 1.5934x; 1.5934x over previous
#include <cuda_runtime.h>
#include <cuda_bf16.h>
#include <math.h>
#include <cstdint>

#define N 8192
#define D 512

// Scratch
__device__ float g_K[(size_t)N * N];              // d2, then fp32 K (in-place)
__device__ __nv_bfloat16 g_Kb[(size_t)N * N];     // bf16 K (upper-triangle tiles only)
__device__ float g_part[64 * (size_t)N];          // symmetric-matvec partials (2MB)
__device__ float g_sq[N];
__device__ float g_u[N];
__device__ float g_v[N];
__device__ int g_maxd2_bits;
__device__ int g_maxP_bits;

__device__ __forceinline__ float2 bf2f(uint32_t u) {
    return __bfloat1622float2(*(const __nv_bfloat162*)&u);
}
__device__ __forceinline__ uint32_t f2tf32(float x) {
    uint32_t r;
    asm("cvt.rna.tf32.f32 %0, %1;" : "=r"(r) : "f"(x));
    return r;
}

// ---------------------------------------------------------------------------
__global__ void k_init() {
    int t = blockIdx.x * blockDim.x + threadIdx.x;
    if (t < N) g_v[t] = 1.0f;
    if (t == 0) { g_maxd2_bits = 0; g_maxP_bits = 0; }
}

__global__ void k_sq(const float* __restrict__ X) {
    int row = blockIdx.x;
    const float4* xr = (const float4*)(X + (size_t)row * D);
    float4 a = xr[threadIdx.x];
    float s = a.x * a.x + a.y * a.y + a.z * a.z + a.w * a.w;
    #pragma unroll
    for (int o = 16; o; o >>= 1) s += __shfl_down_sync(0xffffffffu, s, o);
    __shared__ float sh[4];
    if ((threadIdx.x & 31) == 0) sh[threadIdx.x >> 5] = s;
    __syncthreads();
    if (threadIdx.x == 0) g_sq[row] = sh[0] + sh[1] + sh[2] + sh[3];
}

// ---------------------------------------------------------------------------
// tf32 HMMA GEMM: 128x128 tile / CTA, single product, fp32 accum.
// d2 = sq_i + sq_j - 2*X X^T.  Upper triangle tiles, mirrored via SMEM.
// ---------------------------------------------------------------------------
#define PITCH3 272                 // bytes per SMEM row (64 fl + 16B pad)
#define TILE3  (128 * PITCH3)      // 34816
#define SM_GEMM (2 * TILE3)        // 69632

__device__ __forceinline__ void mma_tf32(float c[4], const uint32_t a[4], const uint32_t b[2]) {
    asm volatile(
        "mma.sync.aligned.m16n8k8.row.col.f32.tf32.tf32.f32 "
        "{%0,%1,%2,%3}, {%4,%5,%6,%7}, {%8,%9}, {%0,%1,%2,%3};"
        : "+f"(c[0]), "+f"(c[1]), "+f"(c[2]), "+f"(c[3])
        : "r"(a[0]), "r"(a[1]), "r"(a[2]), "r"(a[3]), "r"(b[0]), "r"(b[1]));
}

__global__ void __launch_bounds__(256, 2) k_gemm_tf32(const float* __restrict__ X) {
    extern __shared__ __align__(16) char smem[];
    char* sA = smem;
    char* sB = smem + TILE3;

    int tid = threadIdx.x, lane = tid & 31, wid = tid >> 5;
    int wm = wid & 3, wn = wid >> 2;  // 4 x 2 warps -> 32 x 64 per warp

    const int nT = N / 128;  // 64
    int b = blockIdx.x, bi = 0;
    while (b >= nT - bi) { b -= nT - bi; bi++; }
    int bj = bi + b;

    const float* gA = X + (size_t)bi * 128 * D;
    const float* gB = X + (size_t)bj * 128 * D;

    float acc[2][8][4];
    #pragma unroll
    for (int m = 0; m < 2; m++)
        #pragma unroll
        for (int n = 0; n < 8; n++)
            #pragma unroll
            for (int e = 0; e < 4; e++) acc[m][n][e] = 0.f;

    for (int chunk = 0; chunk < 8; chunk++) {
        int k0 = chunk * 64;
        // fill tiles: 128 rows x 64 floats (tf32-rounded), 8 float4 per thread per tile
        #pragma unroll
        for (int t = 0; t < 8; t++) {
            int idx = t * 256 + tid;
            int row = idx >> 4;
            int seg = idx & 15;
            size_t go = (size_t)row * D + k0 + seg * 4;
            float4 a = *(const float4*)(gA + go);
            float4 q = *(const float4*)(gB + go);
            uint32_t so = row * PITCH3 + seg * 16;
            *(uint4*)(sA + so) = make_uint4(f2tf32(a.x), f2tf32(a.y), f2tf32(a.z), f2tf32(a.w));
            *(uint4*)(sB + so) = make_uint4(f2tf32(q.x), f2tf32(q.y), f2tf32(q.z), f2tf32(q.w));
        }
        __syncthreads();

        #pragma unroll
        for (int ks = 0; ks < 8; ks++) {
            int kq = ks * 8 + (lane & 3);          // k element index within chunk
            int ra = wm * 32 + (lane >> 2);
            const char* pa = sA + ra * PITCH3 + kq * 4;
            uint32_t a0[4], a1[4];
            a0[0] = *(const uint32_t*)(pa);
            a0[1] = *(const uint32_t*)(pa + 8 * PITCH3);
            a0[2] = *(const uint32_t*)(pa + 16);
            a0[3] = *(const uint32_t*)(pa + 8 * PITCH3 + 16);
            const char* pa1 = pa + 16 * PITCH3;
            a1[0] = *(const uint32_t*)(pa1);
            a1[1] = *(const uint32_t*)(pa1 + 8 * PITCH3);
            a1[2] = *(const uint32_t*)(pa1 + 16);
            a1[3] = *(const uint32_t*)(pa1 + 8 * PITCH3 + 16);
            #pragma unroll
            for (int nt = 0; nt < 8; nt++) {
                int nb = wn * 64 + nt * 8 + (lane >> 2);
                const char* pb = sB + nb * PITCH3 + kq * 4;
                uint32_t bb[2];
                bb[0] = *(const uint32_t*)(pb);
                bb[1] = *(const uint32_t*)(pb + 16);
                mma_tf32(acc[0][nt], a0, bb);
                mma_tf32(acc[1][nt], a1, bb);
            }
        }
        __syncthreads();
    }

    // Epilogue: d2 = sq_i + sq_j - 2g; store + max; keep d2 in acc for mirror
    int row0 = bi * 128, col0 = bj * 128;
    float mx = 0.f;
    #pragma unroll
    for (int mt = 0; mt < 2; mt++) {
        #pragma unroll
        for (int half = 0; half < 2; half++) {
            int r = row0 + wm * 32 + mt * 16 + half * 8 + (lane >> 2);
            float si = g_sq[r];
            #pragma unroll
            for (int nt = 0; nt < 8; nt++) {
                int c = col0 + wn * 64 + nt * 8 + (lane & 3) * 2;
                float g0 = acc[mt][nt][half * 2 + 0];
                float g1 = acc[mt][nt][half * 2 + 1];
                float v0 = fmaxf(si + __ldg(&g_sq[c + 0]) - 2.f * g0, 0.f);
                float v1 = fmaxf(si + __ldg(&g_sq[c + 1]) - 2.f * g1, 0.f);
                mx = fmaxf(mx, fmaxf(v0, v1));
                acc[mt][nt][half * 2 + 0] = v0;
                acc[mt][nt][half * 2 + 1] = v1;
                *(float2*)&g_K[(size_t)r * N + c] = make_float2(v0, v1);
            }
        }
    }

    if (bi != bj) {  // mirror via SMEM transpose (coalesced write)
        __syncthreads();
        float* smT = (float*)smem;  // pitch 132 floats: 67584 <= 69632
        #pragma unroll
        for (int mt = 0; mt < 2; mt++)
            #pragma unroll
            for (int half = 0; half < 2; half++) {
                int rl = wm * 32 + mt * 16 + half * 8 + (lane >> 2);
                #pragma unroll
                for (int nt = 0; nt < 8; nt++) {
                    int cl = wn * 64 + nt * 8 + (lane & 3) * 2;
                    smT[(cl + 0) * 132 + rl] = acc[mt][nt][half * 2 + 0];
                    smT[(cl + 1) * 132 + rl] = acc[mt][nt][half * 2 + 1];
                }
            }
        __syncthreads();
        #pragma unroll
        for (int t = 0; t < 16; t++) {
            int i = t * 256 + tid;
            int rr = i >> 5;
            int c4 = (i & 31) * 4;
            float4 v = *(float4*)&smT[rr * 132 + c4];
            *(float4*)&g_K[(size_t)(col0 + rr) * N + row0 + c4] = v;
        }
    }

    __shared__ float red[256];
    red[tid] = mx;
    __syncthreads();
    for (int s = 128; s; s >>= 1) {
        if (tid < s) red[tid] = fmaxf(red[tid], red[tid + s]);
        __syncthreads();
    }
    if (tid == 0) atomicMax(&g_maxd2_bits, __float_as_int(red[0]));
}

// ---------------------------------------------------------------------------
// exp pass: K = exp(-10*sqrt(d2)/maxM) fp32 in-place (full) + bf16 copy
// (upper-triangle tiles only), diag -> 0.
// ---------------------------------------------------------------------------
__global__ void k_exp() {
    const float inv_maxM = rsqrtf(__int_as_float(g_maxd2_bits));
    const int total4 = N * (N / 4);
    float4* K4 = (float4*)g_K;
    __nv_bfloat162* Kb2 = (__nv_bfloat162*)g_Kb;
    for (int idx = blockIdx.x * blockDim.x + threadIdx.x; idx < total4;
         idx += gridDim.x * blockDim.x) {
        int lin = idx << 2;
        int row = lin >> 13;
        int col = lin & (N - 1);
        float4 d = K4[idx];
        float4 r;
        r.x = (col + 0 == row) ? 0.f : __expf(-10.f * sqrtf(d.x) * inv_maxM);
        r.y = (col + 1 == row) ? 0.f : __expf(-10.f * sqrtf(d.y) * inv_maxM);
        r.z = (col + 2 == row) ? 0.f : __expf(-10.f * sqrtf(d.z) * inv_maxM);
        r.w = (col + 3 == row) ? 0.f : __expf(-10.f * sqrtf(d.w) * inv_maxM);
        K4[idx] = r;
        if ((col >> 7) >= (row >> 7)) {  // only tiles the matvec reads
            Kb2[idx * 2 + 0] = __nv_bfloat162(__float2bfloat16(r.x), __float2bfloat16(r.y));
            Kb2[idx * 2 + 1] = __nv_bfloat162(__float2bfloat16(r.z), __float2bfloat16(r.w));
        }
    }
}

// ---------------------------------------------------------------------------
// Symmetric matvec, register-resident: CTA = upper-triangle 128x128 tile.
// Thread (rw=tid>>4, cg=tid&15) streams rows 16k+rw, cols [8cg,8cg+8):
// accumulates row partials (shuffle-reduce over cg) and 8 col partials
// (smem-reduce over rw).  Triangle (66MB) stays L2-resident across passes.
// ---------------------------------------------------------------------------
__global__ void __launch_bounds__(256) k_mv_sym(int dir) {
    const float* vin = dir ? g_u : g_v;
    __shared__ float xi[128], xj[128];
    __shared__ float cpb[16 * 136];

    int b = blockIdx.x, bi = 0;
    while (b >= 64 - bi) { b -= 64 - bi; bi++; }
    int bj = bi + b;
    int row0 = bi << 7, col0 = bj << 7;
    int tid = threadIdx.x;
    int rw = tid >> 4, cg = tid & 15;

    if (tid < 128) xi[tid] = vin[row0 + tid];
    else xj[tid - 128] = vin[col0 + tid - 128];
    __syncthreads();

    float4 xj0 = *(float4*)&xj[cg * 8];
    float4 xj1 = *(float4*)&xj[cg * 8 + 4];

    float rs[8];
    float cs[8];
    #pragma unroll
    for (int m = 0; m < 8; m++) cs[m] = 0.f;

    #pragma unroll
    for (int k = 0; k < 8; k++) {
        int r = (k << 4) + rw;
        uint4 kv = __ldg((const uint4*)(g_Kb + (size_t)(row0 + r) * N + col0 + cg * 8));
        float2 p0 = bf2f(kv.x), p1 = bf2f(kv.y), p2 = bf2f(kv.z), p3 = bf2f(kv.w);
        float xir = xi[r];
        float s;
        s = fmaf(p0.x, xj0.x, p0.y * xj0.y);
        s = fmaf(p1.x, xj0.z, s); s = fmaf(p1.y, xj0.w, s);
        s = fmaf(p2.x, xj1.x, s); s = fmaf(p2.y, xj1.y, s);
        s = fmaf(p3.x, xj1.z, s); s = fmaf(p3.y, xj1.w, s);
        rs[k] = s;
        cs[0] = fmaf(p0.x, xir, cs[0]); cs[1] = fmaf(p0.y, xir, cs[1]);
        cs[2] = fmaf(p1.x, xir, cs[2]); cs[3] = fmaf(p1.y, xir, cs[3]);
        cs[4] = fmaf(p2.x, xir, cs[4]); cs[5] = fmaf(p2.y, xir, cs[5]);
        cs[6] = fmaf(p3.x, xir, cs[6]); cs[7] = fmaf(p3.y, xir, cs[7]);
    }

    // row partials: reduce across cg (16 lanes within each half-warp)
    #pragma unroll
    for (int k = 0; k < 8; k++) {
        #pragma unroll
        for (int o = 1; o <= 8; o <<= 1)
            rs[k] += __shfl_xor_sync(0xffffffffu, rs[k], o);
    }
    if (cg == 0) {
        #pragma unroll
        for (int k = 0; k < 8; k++)
            g_part[(size_t)bj * N + row0 + (k << 4) + rw] = rs[k];
    }

    if (bi != bj) {  // col partials -> strip bi
        *(float4*)&cpb[rw * 136 + cg * 8]     = make_float4(cs[0], cs[1], cs[2], cs[3]);
        *(float4*)&cpb[rw * 136 + cg * 8 + 4] = make_float4(cs[4], cs[5], cs[6], cs[7]);
        __syncthreads();
        if (tid < 128) {
            float t = 0.f;
            #pragma unroll
            for (int w = 0; w < 16; w++) t += cpb[w * 136 + tid];
            g_part[(size_t)bi * N + col0 + tid] = t;
        }
    }
}

__global__ void k_mv_reduce(int dir) {
    float* vout = dir ? g_v : g_u;
    int row = (blockIdx.x << 7) + threadIdx.x;
    float s = 0.f;
    #pragma unroll
    for (int k = 0; k < 64; k++) s += g_part[(size_t)k * N + row];
    vout[row] = 1.0f / s;
}

// ---------------------------------------------------------------------------
// maxP over upper-triangle fp32 K tiles, both orientations per entry.
// ---------------------------------------------------------------------------
__global__ void __launch_bounds__(256) k_maxP() {
    __shared__ float ur[128], vr[128], uc[128], vc[128];
    int b = blockIdx.x, bi = 0;
    while (b >= 64 - bi) { b -= 64 - bi; bi++; }
    int bj = bi + b;
    int row0 = bi << 7, col0 = bj << 7;
    int tid = threadIdx.x;
    if (tid < 128) { ur[tid] = g_u[row0 + tid]; vr[tid] = g_v[row0 + tid]; }
    else { uc[tid - 128] = g_u[col0 + tid - 128]; vc[tid - 128] = g_v[col0 + tid - 128]; }
    __syncthreads();

    float m = 0.f;
    #pragma unroll
    for (int t = 0; t < 16; t++) {
        int idx = t * 256 + tid;          // over 4096 float4
        int r = idx >> 5;
        int c = (idx & 31) * 4;
        float4 k = *(const float4*)&g_K[(size_t)(row0 + r) * N + col0 + c];
        float urr = ur[r], vrr = vr[r];
        m = fmaxf(m, fmaxf(urr * k.x * vc[c + 0], uc[c + 0] * k.x * vrr));
        m = fmaxf(m, fmaxf(urr * k.y * vc[c + 1], uc[c + 1] * k.y * vrr));
        m = fmaxf(m, fmaxf(urr * k.z * vc[c + 2], uc[c + 2] * k.z * vrr));
        m = fmaxf(m, fmaxf(urr * k.w * vc[c + 3], uc[c + 3] * k.w * vrr));
    }
    #pragma unroll
    for (int o = 16; o; o >>= 1) m = fmaxf(m, __shfl_down_sync(0xffffffffu, m, o));
    __shared__ float sh[8];
    if ((tid & 31) == 0) sh[tid >> 5] = m;
    __syncthreads();
    if (tid < 8) {
        float t = sh[tid];
        #pragma unroll
        for (int o = 4; o; o >>= 1) t = fmaxf(t, __shfl_down_sync(0xffu, t, o));
        if (tid == 0) atomicMax(&g_maxP_bits, __float_as_int(t));
    }
}

__global__ void k_final(float* __restrict__ out) {
    const float invP = 1.0f / __int_as_float(g_maxP_bits);
    const int total4 = N * (N / 4);
    const float4* K4 = (const float4*)g_K;
    float4* O4 = (float4*)out;
    for (int idx = blockIdx.x * blockDim.x + threadIdx.x; idx < total4;
         idx += gridDim.x * blockDim.x) {
        int lin = idx << 2;
        int row = lin >> 13;
        int col = lin & (N - 1);
        float u = __ldg(&g_u[row]);
        float4 k = K4[idx];
        float4 vv = *(const float4*)(g_v + col);
        float4 r;
        r.x = (col + 0 == row) ? 1.f : u * k.x * vv.x * invP;
        r.y = (col + 1 == row) ? 1.f : u * k.y * vv.y * invP;
        r.z = (col + 2 == row) ? 1.f : u * k.z * vv.z * invP;
        r.w = (col + 3 == row) ? 1.f : u * k.w * vv.w * invP;
        O4[idx] = r;
    }
}

// ---------------------------------------------------------------------------
extern "C" void kernel_launch(void* const* d_in, const int* in_sizes, int n_in,
                              void* d_out, int out_size) {
    const float* X = (const float*)d_in[0];
    float* out = (float*)d_out;

    cudaFuncSetAttribute(k_gemm_tf32, cudaFuncAttributeMaxDynamicSharedMemorySize, SM_GEMM);

    k_init<<<(N + 255) / 256, 256>>>();
    k_sq<<<N, 128>>>(X);
    k_gemm_tf32<<<(64 * 65) / 2, 256, SM_GEMM>>>(X);
    k_exp<<<8192, 256>>>();
    for (int it = 0; it < 10; it++) {
        k_mv_sym<<<(64 * 65) / 2, 256>>>(0);   // partials of K*v
        k_mv_reduce<<<64, 128>>>(0);           // u = 1/(K v)
        k_mv_sym<<<(64 * 65) / 2, 256>>>(1);   // partials of K*u
        k_mv_reduce<<<64, 128>>>(1);           // v = 1/(K u)
    }
    k_maxP<<<(64 * 65) / 2, 256>>>();
    k_final<<<8192, 256>>>(out);
}

// round 17
// speedup vs baseline: 1.6088x; 1.0097x over previous
#include <cuda_runtime.h>
#include <cuda_bf16.h>
#include <math.h>
#include <cstdint>

#define N 8192
#define D 512

// Scratch
__device__ float g_K[(size_t)N * N];              // d2 (kept through whole pipeline)
__device__ __nv_bfloat16 g_Kb[(size_t)N * N];     // bf16 K (upper-triangle 256-tiles only)
__device__ float g_part[32 * (size_t)N];          // symmetric-matvec partials (1MB)
__device__ float g_sq[N];
__device__ float g_u[N];
__device__ float g_v[N];
__device__ int g_maxd2_bits;
__device__ int g_maxP_bits;

__device__ __forceinline__ float2 bf2f(uint32_t u) {
    return __bfloat1622float2(*(const __nv_bfloat162*)&u);
}
__device__ __forceinline__ uint32_t f2tf32(float x) {
    uint32_t r;
    asm("cvt.rna.tf32.f32 %0, %1;" : "=r"(r) : "f"(x));
    return r;
}

// ---------------------------------------------------------------------------
__global__ void k_init() {
    int t = blockIdx.x * blockDim.x + threadIdx.x;
    if (t < N) g_v[t] = 1.0f;
    if (t == 0) { g_maxd2_bits = 0; g_maxP_bits = 0; }
}

__global__ void k_sq(const float* __restrict__ X) {
    int row = blockIdx.x;
    const float4* xr = (const float4*)(X + (size_t)row * D);
    float4 a = xr[threadIdx.x];
    float s = a.x * a.x + a.y * a.y + a.z * a.z + a.w * a.w;
    #pragma unroll
    for (int o = 16; o; o >>= 1) s += __shfl_down_sync(0xffffffffu, s, o);
    __shared__ float sh[4];
    if ((threadIdx.x & 31) == 0) sh[threadIdx.x >> 5] = s;
    __syncthreads();
    if (threadIdx.x == 0) g_sq[row] = sh[0] + sh[1] + sh[2] + sh[3];
}

// ---------------------------------------------------------------------------
// tf32 HMMA GEMM: 128x128 tile / CTA, single product, fp32 accum.
// d2 = sq_i + sq_j - 2*X X^T.  Upper triangle tiles, mirrored via SMEM.
// ---------------------------------------------------------------------------
#define PITCH3 272                 // bytes per SMEM row (64 fl + 16B pad)
#define TILE3  (128 * PITCH3)      // 34816
#define SM_GEMM (2 * TILE3)        // 69632

__device__ __forceinline__ void mma_tf32(float c[4], const uint32_t a[4], const uint32_t b[2]) {
    asm volatile(
        "mma.sync.aligned.m16n8k8.row.col.f32.tf32.tf32.f32 "
        "{%0,%1,%2,%3}, {%4,%5,%6,%7}, {%8,%9}, {%0,%1,%2,%3};"
        : "+f"(c[0]), "+f"(c[1]), "+f"(c[2]), "+f"(c[3])
        : "r"(a[0]), "r"(a[1]), "r"(a[2]), "r"(a[3]), "r"(b[0]), "r"(b[1]));
}

__global__ void __launch_bounds__(256, 2) k_gemm_tf32(const float* __restrict__ X) {
    extern __shared__ __align__(16) char smem[];
    char* sA = smem;
    char* sB = smem + TILE3;

    int tid = threadIdx.x, lane = tid & 31, wid = tid >> 5;
    int wm = wid & 3, wn = wid >> 2;  // 4 x 2 warps -> 32 x 64 per warp

    const int nT = N / 128;  // 64
    int b = blockIdx.x, bi = 0;
    while (b >= nT - bi) { b -= nT - bi; bi++; }
    int bj = bi + b;

    const float* gA = X + (size_t)bi * 128 * D;
    const float* gB = X + (size_t)bj * 128 * D;

    float acc[2][8][4];
    #pragma unroll
    for (int m = 0; m < 2; m++)
        #pragma unroll
        for (int n = 0; n < 8; n++)
            #pragma unroll
            for (int e = 0; e < 4; e++) acc[m][n][e] = 0.f;

    for (int chunk = 0; chunk < 8; chunk++) {
        int k0 = chunk * 64;
        #pragma unroll
        for (int t = 0; t < 8; t++) {
            int idx = t * 256 + tid;
            int row = idx >> 4;
            int seg = idx & 15;
            size_t go = (size_t)row * D + k0 + seg * 4;
            float4 a = *(const float4*)(gA + go);
            float4 q = *(const float4*)(gB + go);
            uint32_t so = row * PITCH3 + seg * 16;
            *(uint4*)(sA + so) = make_uint4(f2tf32(a.x), f2tf32(a.y), f2tf32(a.z), f2tf32(a.w));
            *(uint4*)(sB + so) = make_uint4(f2tf32(q.x), f2tf32(q.y), f2tf32(q.z), f2tf32(q.w));
        }
        __syncthreads();

        #pragma unroll
        for (int ks = 0; ks < 8; ks++) {
            int kq = ks * 8 + (lane & 3);
            int ra = wm * 32 + (lane >> 2);
            const char* pa = sA + ra * PITCH3 + kq * 4;
            uint32_t a0[4], a1[4];
            a0[0] = *(const uint32_t*)(pa);
            a0[1] = *(const uint32_t*)(pa + 8 * PITCH3);
            a0[2] = *(const uint32_t*)(pa + 16);
            a0[3] = *(const uint32_t*)(pa + 8 * PITCH3 + 16);
            const char* pa1 = pa + 16 * PITCH3;
            a1[0] = *(const uint32_t*)(pa1);
            a1[1] = *(const uint32_t*)(pa1 + 8 * PITCH3);
            a1[2] = *(const uint32_t*)(pa1 + 16);
            a1[3] = *(const uint32_t*)(pa1 + 8 * PITCH3 + 16);
            #pragma unroll
            for (int nt = 0; nt < 8; nt++) {
                int nb = wn * 64 + nt * 8 + (lane >> 2);
                const char* pb = sB + nb * PITCH3 + kq * 4;
                uint32_t bb[2];
                bb[0] = *(const uint32_t*)(pb);
                bb[1] = *(const uint32_t*)(pb + 16);
                mma_tf32(acc[0][nt], a0, bb);
                mma_tf32(acc[1][nt], a1, bb);
            }
        }
        __syncthreads();
    }

    int row0 = bi * 128, col0 = bj * 128;
    float mx = 0.f;
    #pragma unroll
    for (int mt = 0; mt < 2; mt++) {
        #pragma unroll
        for (int half = 0; half < 2; half++) {
            int r = row0 + wm * 32 + mt * 16 + half * 8 + (lane >> 2);
            float si = g_sq[r];
            #pragma unroll
            for (int nt = 0; nt < 8; nt++) {
                int c = col0 + wn * 64 + nt * 8 + (lane & 3) * 2;
                float g0 = acc[mt][nt][half * 2 + 0];
                float g1 = acc[mt][nt][half * 2 + 1];
                float v0 = fmaxf(si + __ldg(&g_sq[c + 0]) - 2.f * g0, 0.f);
                float v1 = fmaxf(si + __ldg(&g_sq[c + 1]) - 2.f * g1, 0.f);
                mx = fmaxf(mx, fmaxf(v0, v1));
                acc[mt][nt][half * 2 + 0] = v0;
                acc[mt][nt][half * 2 + 1] = v1;
                *(float2*)&g_K[(size_t)r * N + c] = make_float2(v0, v1);
            }
        }
    }

    if (bi != bj) {  // mirror via SMEM transpose (coalesced write)
        __syncthreads();
        float* smT = (float*)smem;
        #pragma unroll
        for (int mt = 0; mt < 2; mt++)
            #pragma unroll
            for (int half = 0; half < 2; half++) {
                int rl = wm * 32 + mt * 16 + half * 8 + (lane >> 2);
                #pragma unroll
                for (int nt = 0; nt < 8; nt++) {
                    int cl = wn * 64 + nt * 8 + (lane & 3) * 2;
                    smT[(cl + 0) * 132 + rl] = acc[mt][nt][half * 2 + 0];
                    smT[(cl + 1) * 132 + rl] = acc[mt][nt][half * 2 + 1];
                }
            }
        __syncthreads();
        #pragma unroll
        for (int t = 0; t < 16; t++) {
            int i = t * 256 + tid;
            int rr = i >> 5;
            int c4 = (i & 31) * 4;
            float4 v = *(float4*)&smT[rr * 132 + c4];
            *(float4*)&g_K[(size_t)(col0 + rr) * N + row0 + c4] = v;
        }
    }

    __shared__ float red[256];
    red[tid] = mx;
    __syncthreads();
    for (int s = 128; s; s >>= 1) {
        if (tid < s) red[tid] = fmaxf(red[tid], red[tid + s]);
        __syncthreads();
    }
    if (tid == 0) atomicMax(&g_maxd2_bits, __float_as_int(red[0]));
}

// ---------------------------------------------------------------------------
// exp pass (triangle 256-tiles only): Kb = bf16(exp(-10*sqrt(d2)/maxM)),
// diag -> 0.  d2 stays untouched in g_K.
// ---------------------------------------------------------------------------
__global__ void __launch_bounds__(256) k_exp() {
    const float inv_maxM = rsqrtf(__int_as_float(g_maxd2_bits));
    int b = blockIdx.x, bi = 0;
    while (b >= 32 - bi) { b -= 32 - bi; bi++; }
    int bj = bi + b;
    int row0 = bi << 8, col0 = bj << 8;
    int tid = threadIdx.x;

    #pragma unroll
    for (int t = 0; t < 64; t++) {
        int idx = t * 256 + tid;       // over 16384 float4 of a 256x256 tile
        int r = idx >> 6;
        int c4 = (idx & 63) * 4;
        int grow = row0 + r;
        int gcol = col0 + c4;
        float4 d = *(const float4*)&g_K[(size_t)grow * N + gcol];
        float e0 = (gcol + 0 == grow) ? 0.f : __expf(-10.f * sqrtf(d.x) * inv_maxM);
        float e1 = (gcol + 1 == grow) ? 0.f : __expf(-10.f * sqrtf(d.y) * inv_maxM);
        float e2 = (gcol + 2 == grow) ? 0.f : __expf(-10.f * sqrtf(d.z) * inv_maxM);
        float e3 = (gcol + 3 == grow) ? 0.f : __expf(-10.f * sqrtf(d.w) * inv_maxM);
        __nv_bfloat162* kb = (__nv_bfloat162*)(g_Kb + (size_t)grow * N + gcol);
        kb[0] = __nv_bfloat162(__float2bfloat16(e0), __float2bfloat16(e1));
        kb[1] = __nv_bfloat162(__float2bfloat16(e2), __float2bfloat16(e3));
    }
}

// ---------------------------------------------------------------------------
// Symmetric matvec, 256x256 tiles (528 CTAs ~ 1.2 waves).
// Thread (rw=tid>>4, cg=tid&15): 16 rows x cols [16cg,16cg+16).
// Row partials shuffle-reduced over cg; col partials smem-reduced over rw.
// g_part[s][i], 32 strips; every slot written exactly once.
// ---------------------------------------------------------------------------
__global__ void __launch_bounds__(256) k_mv_sym(int dir) {
    const float* vin = dir ? g_u : g_v;
    __shared__ float xi[256], xj[256];
    __shared__ float cpb[16 * 264];

    int b = blockIdx.x, bi = 0;
    while (b >= 32 - bi) { b -= 32 - bi; bi++; }
    int bj = bi + b;
    int row0 = bi << 8, col0 = bj << 8;
    int tid = threadIdx.x;
    int rw = tid >> 4, cg = tid & 15;

    xi[tid] = vin[row0 + tid];
    xj[tid] = vin[col0 + tid];
    __syncthreads();

    float xjl[16];
    #pragma unroll
    for (int j = 0; j < 16; j++) xjl[j] = xj[cg * 16 + j];

    float rs[16], cs[16];
    #pragma unroll
    for (int m = 0; m < 16; m++) cs[m] = 0.f;

    #pragma unroll
    for (int k = 0; k < 16; k++) {
        int r = (k << 4) + rw;
        const uint4* p = (const uint4*)(g_Kb + (size_t)(row0 + r) * N + col0 + cg * 16);
        uint4 k0 = __ldg(&p[0]);
        uint4 k1 = __ldg(&p[1]);
        float xir = xi[r];
        float s = 0.f;
        float2 q;
        q = bf2f(k0.x); s = fmaf(q.x, xjl[0], s); s = fmaf(q.y, xjl[1], s);
                        cs[0] = fmaf(q.x, xir, cs[0]); cs[1] = fmaf(q.y, xir, cs[1]);
        q = bf2f(k0.y); s = fmaf(q.x, xjl[2], s); s = fmaf(q.y, xjl[3], s);
                        cs[2] = fmaf(q.x, xir, cs[2]); cs[3] = fmaf(q.y, xir, cs[3]);
        q = bf2f(k0.z); s = fmaf(q.x, xjl[4], s); s = fmaf(q.y, xjl[5], s);
                        cs[4] = fmaf(q.x, xir, cs[4]); cs[5] = fmaf(q.y, xir, cs[5]);
        q = bf2f(k0.w); s = fmaf(q.x, xjl[6], s); s = fmaf(q.y, xjl[7], s);
                        cs[6] = fmaf(q.x, xir, cs[6]); cs[7] = fmaf(q.y, xir, cs[7]);
        q = bf2f(k1.x); s = fmaf(q.x, xjl[8], s); s = fmaf(q.y, xjl[9], s);
                        cs[8] = fmaf(q.x, xir, cs[8]); cs[9] = fmaf(q.y, xir, cs[9]);
        q = bf2f(k1.y); s = fmaf(q.x, xjl[10], s); s = fmaf(q.y, xjl[11], s);
                        cs[10] = fmaf(q.x, xir, cs[10]); cs[11] = fmaf(q.y, xir, cs[11]);
        q = bf2f(k1.z); s = fmaf(q.x, xjl[12], s); s = fmaf(q.y, xjl[13], s);
                        cs[12] = fmaf(q.x, xir, cs[12]); cs[13] = fmaf(q.y, xir, cs[13]);
        q = bf2f(k1.w); s = fmaf(q.x, xjl[14], s); s = fmaf(q.y, xjl[15], s);
                        cs[14] = fmaf(q.x, xir, cs[14]); cs[15] = fmaf(q.y, xir, cs[15]);
        rs[k] = s;
    }

    // row partials: reduce across cg (low 4 lane bits)
    #pragma unroll
    for (int k = 0; k < 16; k++) {
        #pragma unroll
        for (int o = 1; o <= 8; o <<= 1)
            rs[k] += __shfl_xor_sync(0xffffffffu, rs[k], o);
    }
    if (cg == 0) {
        #pragma unroll
        for (int k = 0; k < 16; k++)
            g_part[(size_t)bj * N + row0 + (k << 4) + rw] = rs[k];
    }

    if (bi != bj) {  // col partials -> strip bi
        #pragma unroll
        for (int m = 0; m < 16; m += 4)
            *(float4*)&cpb[rw * 264 + cg * 16 + m] =
                make_float4(cs[m], cs[m + 1], cs[m + 2], cs[m + 3]);
        __syncthreads();
        float t = 0.f;
        #pragma unroll
        for (int w = 0; w < 16; w++) t += cpb[w * 264 + tid];
        g_part[(size_t)bi * N + col0 + tid] = t;
    }
}

__global__ void k_mv_reduce(int dir) {
    float* vout = dir ? g_v : g_u;
    int row = (blockIdx.x << 7) + threadIdx.x;
    float s = 0.f;
    #pragma unroll
    for (int k = 0; k < 32; k++) s += g_part[(size_t)k * N + row];
    vout[row] = 1.0f / s;
}

// ---------------------------------------------------------------------------
// maxP over upper-triangle 128-tiles of d2, exp recomputed, both orientations.
// ---------------------------------------------------------------------------
__global__ void __launch_bounds__(256) k_maxP() {
    const float inv_maxM = rsqrtf(__int_as_float(g_maxd2_bits));
    __shared__ float ur[128], vr[128], uc[128], vc[128];
    int b = blockIdx.x, bi = 0;
    while (b >= 64 - bi) { b -= 64 - bi; bi++; }
    int bj = bi + b;
    int row0 = bi << 7, col0 = bj << 7;
    int tid = threadIdx.x;
    if (tid < 128) { ur[tid] = g_u[row0 + tid]; vr[tid] = g_v[row0 + tid]; }
    else { uc[tid - 128] = g_u[col0 + tid - 128]; vc[tid - 128] = g_v[col0 + tid - 128]; }
    __syncthreads();

    float m = 0.f;
    #pragma unroll
    for (int t = 0; t < 16; t++) {
        int idx = t * 256 + tid;
        int r = idx >> 5;
        int c = (idx & 31) * 4;
        float4 d = *(const float4*)&g_K[(size_t)(row0 + r) * N + col0 + c];
        float e0 = __expf(-10.f * sqrtf(d.x) * inv_maxM);
        float e1 = __expf(-10.f * sqrtf(d.y) * inv_maxM);
        float e2 = __expf(-10.f * sqrtf(d.z) * inv_maxM);
        float e3 = __expf(-10.f * sqrtf(d.w) * inv_maxM);
        if (bi == bj) {  // exclude diagonal entries
            if (r == c + 0) e0 = 0.f;
            if (r == c + 1) e1 = 0.f;
            if (r == c + 2) e2 = 0.f;
            if (r == c + 3) e3 = 0.f;
        }
        float urr = ur[r], vrr = vr[r];
        m = fmaxf(m, fmaxf(urr * e0 * vc[c + 0], uc[c + 0] * e0 * vrr));
        m = fmaxf(m, fmaxf(urr * e1 * vc[c + 1], uc[c + 1] * e1 * vrr));
        m = fmaxf(m, fmaxf(urr * e2 * vc[c + 2], uc[c + 2] * e2 * vrr));
        m = fmaxf(m, fmaxf(urr * e3 * vc[c + 3], uc[c + 3] * e3 * vrr));
    }
    #pragma unroll
    for (int o = 16; o; o >>= 1) m = fmaxf(m, __shfl_down_sync(0xffffffffu, m, o));
    __shared__ float sh[8];
    if ((tid & 31) == 0) sh[tid >> 5] = m;
    __syncthreads();
    if (tid < 8) {
        float t = sh[tid];
        #pragma unroll
        for (int o = 4; o; o >>= 1) t = fmaxf(t, __shfl_down_sync(0xffu, t, o));
        if (tid == 0) atomicMax(&g_maxP_bits, __float_as_int(t));
    }
}

// ---------------------------------------------------------------------------
// final: P = u_i exp(-10 sqrt(d2)/maxM) v_j / maxP, diag -> 1
// ---------------------------------------------------------------------------
__global__ void k_final(float* __restrict__ out) {
    const float inv_maxM = rsqrtf(__int_as_float(g_maxd2_bits));
    const float invP = 1.0f / __int_as_float(g_maxP_bits);
    const int total4 = N * (N / 4);
    const float4* K4 = (const float4*)g_K;
    float4* O4 = (float4*)out;
    for (int idx = blockIdx.x * blockDim.x + threadIdx.x; idx < total4;
         idx += gridDim.x * blockDim.x) {
        int lin = idx << 2;
        int row = lin >> 13;
        int col = lin & (N - 1);
        float u = __ldg(&g_u[row]);
        float4 d = K4[idx];
        float4 vv = *(const float4*)(g_v + col);
        float4 r;
        r.x = (col + 0 == row) ? 1.f : u * __expf(-10.f * sqrtf(d.x) * inv_maxM) * vv.x * invP;
        r.y = (col + 1 == row) ? 1.f : u * __expf(-10.f * sqrtf(d.y) * inv_maxM) * vv.y * invP;
        r.z = (col + 2 == row) ? 1.f : u * __expf(-10.f * sqrtf(d.z) * inv_maxM) * vv.z * invP;
        r.w = (col + 3 == row) ? 1.f : u * __expf(-10.f * sqrtf(d.w) * inv_maxM) * vv.w * invP;
        O4[idx] = r;
    }
}

// ---------------------------------------------------------------------------
extern "C" void kernel_launch(void* const* d_in, const int* in_sizes, int n_in,
                              void* d_out, int out_size) {
    const float* X = (const float*)d_in[0];
    float* out = (float*)d_out;

    cudaFuncSetAttribute(k_gemm_tf32, cudaFuncAttributeMaxDynamicSharedMemorySize, SM_GEMM);

    k_init<<<(N + 255) / 256, 256>>>();
    k_sq<<<N, 128>>>(X);
    k_gemm_tf32<<<(64 * 65) / 2, 256, SM_GEMM>>>(X);
    k_exp<<<(32 * 33) / 2, 256>>>();
    for (int it = 0; it < 10; it++) {
        k_mv_sym<<<(32 * 33) / 2, 256>>>(0);   // partials of K*v
        k_mv_reduce<<<64, 128>>>(0);           // u = 1/(K v)
        k_mv_sym<<<(32 * 33) / 2, 256>>>(1);   // partials of K*u
        k_mv_reduce<<<64, 128>>>(1);           // v = 1/(K u)
    }
    k_maxP<<<(64 * 65) / 2, 256>>>();
    k_final<<<8192, 256>>>(out);
}